// round 15
// baseline (speedup 1.0000x reference)
#include <cuda_runtime.h>
#include <cuda_bf16.h>
#include <cstdint>

#define G  32
#define NV 64
#define H  256
#define M_ROWS (G * NV)

// Scratch (allocation-free rule: __device__ globals)
__device__ float g_C[M_ROWS * H];
__device__ float g_Y[M_ROWS * H];

// ---------------------------------------------------------------------------
// Stage A: TF32 tensor-core GEMM, no explicit CVT (HMMA.tf32 reads top 19 bits).
//   out[m][n] = sum_h z[m][h] * W[n][h] + b[n]
// Block tile 64(M) x 64(N), KC=32 double-buffered cp.async, 8 warps,
// warp tile 16(M) x 32(N). Grid (H/64, M/64, 2) = 256 blocks.
// ---------------------------------------------------------------------------
#define KC   32
#define LDK  36
#define NCH  (H / KC)   // 8 chunks

__device__ __forceinline__ void cpa16(uint32_t dst, const float* src) {
    asm volatile("cp.async.cg.shared.global [%0], [%1], 16;" :: "r"(dst), "l"(src));
}

__device__ __forceinline__ void mma_tf32(float c[4], const uint32_t a[4], const uint32_t b[2]) {
    asm volatile(
        "mma.sync.aligned.m16n8k8.row.col.f32.tf32.tf32.f32 "
        "{%0,%1,%2,%3}, {%4,%5,%6,%7}, {%8,%9}, {%0,%1,%2,%3};"
        : "+f"(c[0]), "+f"(c[1]), "+f"(c[2]), "+f"(c[3])
        : "r"(a[0]), "r"(a[1]), "r"(a[2]), "r"(a[3]), "r"(b[0]), "r"(b[1]));
}

__global__ void __launch_bounds__(256, 2) gemm_tc_kernel(
    const float* __restrict__ z,
    const float* __restrict__ Wc, const float* __restrict__ bc,
    const float* __restrict__ Wy, const float* __restrict__ by)
{
    const float* __restrict__ W    = blockIdx.z ? Wy : Wc;
    const float* __restrict__ bias = blockIdx.z ? by : bc;
    float* __restrict__ outp       = blockIdx.z ? g_Y : g_C;

    __shared__ float As[2][64 * LDK];
    __shared__ float Bs[2][64 * LDK];

    const int t    = threadIdx.x;
    const int warp = t >> 5;
    const int lane = t & 31;
    const int g    = lane >> 2;
    const int tg   = lane & 3;
    const int wm   = warp & 3;
    const int wn   = warp >> 2;
    const int m0   = blockIdx.y * 64;
    const int n0   = blockIdx.x * 64;

    const int r0s = t >> 3,         kg0 = t & 7;
    const int r1s = (t + 256) >> 3, kg1 = (t + 256) & 7;

    float acc[4][4];
#pragma unroll
    for (int nt = 0; nt < 4; nt++)
#pragma unroll
        for (int i = 0; i < 4; i++) acc[nt][i] = 0.0f;

    auto issue = [&](int c) {
        const int buf = c & 1;
        const int kc0 = c * KC;
        uint32_t asb = (uint32_t)__cvta_generic_to_shared(&As[buf][0]);
        uint32_t bsb = (uint32_t)__cvta_generic_to_shared(&Bs[buf][0]);
        cpa16(asb + (uint32_t)(r0s * LDK + kg0 * 4) * 4, z + (size_t)(m0 + r0s) * H + kc0 + kg0 * 4);
        cpa16(asb + (uint32_t)(r1s * LDK + kg1 * 4) * 4, z + (size_t)(m0 + r1s) * H + kc0 + kg1 * 4);
        cpa16(bsb + (uint32_t)(r0s * LDK + kg0 * 4) * 4, W + (size_t)(n0 + r0s) * H + kc0 + kg0 * 4);
        cpa16(bsb + (uint32_t)(r1s * LDK + kg1 * 4) * 4, W + (size_t)(n0 + r1s) * H + kc0 + kg1 * 4);
        asm volatile("cp.async.commit_group;");
    };

    issue(0);

    for (int c = 0; c < NCH; c++) {
        if (c + 1 < NCH) {
            issue(c + 1);
            asm volatile("cp.async.wait_group 1;");
        } else {
            asm volatile("cp.async.wait_group 0;");
        }
        __syncthreads();

        const uint32_t* as = reinterpret_cast<const uint32_t*>(&As[c & 1][0]);
        const uint32_t* bs = reinterpret_cast<const uint32_t*>(&Bs[c & 1][0]);

#pragma unroll
        for (int ks = 0; ks < KC / 8; ks++) {
            const int kk = ks * 8;
            uint32_t afr[4];
            {
                const uint32_t* ap = as + (wm * 16 + g) * LDK + kk + tg;
                afr[0] = ap[0];
                afr[1] = ap[8 * LDK];
                afr[2] = ap[4];
                afr[3] = ap[8 * LDK + 4];
            }
            uint32_t bfr[4][2];
#pragma unroll
            for (int nt = 0; nt < 4; nt++) {
                const uint32_t* bp = bs + (wn * 32 + nt * 8 + g) * LDK + kk + tg;
                bfr[nt][0] = bp[0];
                bfr[nt][1] = bp[4];
            }
#pragma unroll
            for (int nt = 0; nt < 4; nt++)
                mma_tf32(acc[nt], afr, bfr[nt]);
        }
        __syncthreads();
    }

#pragma unroll
    for (int nt = 0; nt < 4; nt++) {
        const int col = n0 + wn * 32 + nt * 8 + 2 * tg;
        const float b0 = __ldg(&bias[col]);
        const float b1 = __ldg(&bias[col + 1]);
        const int row = m0 + wm * 16 + g;
        float2 o0 = {acc[nt][0] + b0, acc[nt][1] + b1};
        float2 o1 = {acc[nt][2] + b0, acc[nt][3] + b1};
        *reinterpret_cast<float2*>(&outp[(size_t)row * H + col])       = o0;
        *reinterpret_cast<float2*>(&outp[(size_t)(row + 8) * H + col]) = o1;
    }
}

// ---------------------------------------------------------------------------
// Stage B: pairwise sigmoid sum (R12 structure, EX2+RCP sigmoid).
// sigma(x) = 1 / (1 + exp2(-x*log2e))  -> FFMA + MUFU.EX2 + FADD + MUFU.RCP
// (two fast rt=8 MUFU ops instead of one slow MUFU.TANH).
// Block = 256 threads = 32 float2-cols x 8 rows (warp w owns row r0+w),
// quarter of H per block (HB=64 floats) -> 16 KB smem, grid (8,32,4)=1024.
// One compacted cp.async fill, C-row load overlapped, linear LDS.64 loop.
// ---------------------------------------------------------------------------
#define RPB  8
#define HB   64          // h floats per block
#define HB2  (HB / 2)    // float2 cols per block = 32
#define NL2E (-1.4426950408889634f)

__device__ __forceinline__ float ex2(float x) {
    float r;
    asm("ex2.approx.f32 %0, %1;" : "=f"(r) : "f"(x));
    return r;
}
__device__ __forceinline__ float rcp(float x) {
    float r;
    asm("rcp.approx.f32 %0, %1;" : "=f"(r) : "f"(x));
    return r;
}
// sigma(c+y) with cpre = -c*log2e precomputed
__device__ __forceinline__ float sigm(float y, float cpre) {
    return rcp(1.0f + ex2(fmaf(y, NL2E, cpre)));
}

__global__ void __launch_bounds__(256) attn_kernel(
    const float* __restrict__ mask, float* __restrict__ out)
{
    extern __shared__ float ysh[];       // [NV rows][64 floats] compacted
    __shared__ int acts[NV];
    __shared__ int s_cnt[2];
    __shared__ int s_nact;

    const int gg  = blockIdx.y;
    const int r0  = blockIdx.x * RPB;
    const int hb  = blockIdx.z;          // h quarter
    const int t   = threadIdx.x;
    const int col = t & 31;              // float2 col within quarter
    const int r   = t >> 5;              // 0..7 row slot (== warp id)

    // ---- in-block compaction (threads 0..63; syncs unguarded) ----
    bool act = false;
    unsigned bal = 0;
    if (t < NV) {
        act = (mask[gg * NV + t] > 0.5f);
        bal = __ballot_sync(0xffffffffu, act);
        if ((t & 31) == 0) s_cnt[t >> 5] = __popc(bal);
    }
    __syncthreads();
    if (t < NV) {
        const int warp = t >> 5, lane = t & 31;
        const int a0 = s_cnt[0], a1 = s_cnt[1];
        const int nact = a0 + a1;
        const int pre  = __popc(bal & ((1u << lane) - 1u));
        const int preI = lane - pre;
        const int pos = act ? ((warp ? a0 : 0) + pre)
                            : (nact + (warp ? (32 - a0) : 0) + preI);
        acts[pos] = t;
        if (t == 0) s_nact = nact;
    }
    __syncthreads();

    const int nact  = s_nact;
    const int rr    = r0 + r;
    const int row_i = acts[rr];          // rr <= 63 always

    float2* __restrict__ outp = reinterpret_cast<float2*>(
        out + (size_t)gg * NV * H + (size_t)row_i * H + hb * HB) + col;

    if (r0 >= nact) {                    // fully inactive block
        outp[0] = make_float2(0.0f, 0.0f);
        return;
    }

    // ---- compacted fill (issue), then C-row load (overlaps), then wait ----
    {
        const float* __restrict__ ygb = g_Y + (size_t)gg * NV * H + hb * HB;
        const uint32_t sb = (uint32_t)__cvta_generic_to_shared(&ysh[0]);
        const int nch = nact * (HB / 4);          // 16B chunks (16 per row)
        for (int s = t; s < nch; s += 256) {
            const int rw = s >> 4;
            const int q  = s & 15;
            cpa16(sb + (uint32_t)(rw * HB + q * 4) * 4,
                  ygb + (size_t)acts[rw] * H + q * 4);
        }
        asm volatile("cp.async.commit_group;");
    }

    float2 cpre, acc;
    {
        const float2 c = __ldg(reinterpret_cast<const float2*>(
            g_C + (size_t)gg * NV * H + (size_t)row_i * H + hb * HB) + col);
        cpre.x = NL2E * c.x;
        cpre.y = NL2E * c.y;
        acc.x = 0.0f;
        acc.y = 0.0f;
    }

    asm volatile("cp.async.wait_group 0;");
    __syncthreads();

    const float2* __restrict__ ys2 = reinterpret_cast<const float2*>(ysh);

    int jj = 0;
    for (; jj + 8 <= nact; jj += 8) {
        float2 yv[8];
#pragma unroll
        for (int u = 0; u < 8; u++) yv[u] = ys2[(jj + u) * HB2 + col];
#pragma unroll
        for (int u = 0; u < 8; u++) {
            acc.x += sigm(yv[u].x, cpre.x);
            acc.y += sigm(yv[u].y, cpre.y);
        }
    }
    for (; jj < nact; jj++) {
        const float2 y = ys2[jj * HB2 + col];
        acc.x += sigm(y.x, cpre.x);
        acc.y += sigm(y.y, cpre.y);
    }

    const float inv = 1.0f / (float)nact;
    float2 v;
    if (rr < nact) {                     // straddling block's tail rows -> 0
        v.x = acc.x * inv;
        v.y = acc.y * inv;
    } else {
        v.x = 0.0f;
        v.y = 0.0f;
    }
    outp[0] = v;
}

// ---------------------------------------------------------------------------
// kernel_launch
// ---------------------------------------------------------------------------
extern "C" void kernel_launch(void* const* d_in, const int* in_sizes, int n_in,
                              void* d_out, int out_size)
{
    const float *z = nullptr, *mask = nullptr;
    const float *Wc = nullptr, *bc = nullptr, *Wy = nullptr, *by = nullptr;

    for (int i = 0; i < n_in; i++) {
        int s = in_sizes[i];
        const float* p = (const float*)d_in[i];
        if (s == M_ROWS * H)       z = p;
        else if (s == M_ROWS)      mask = p;
        else if (s == H * H)       { if (!Wc) Wc = p; else Wy = p; }
        else if (s == H)           { if (!bc) bc = p; else by = p; }
    }

    float* out = (float*)d_out;

    gemm_tc_kernel<<<dim3(H / 64, M_ROWS / 64, 2), 256>>>(z, Wc, bc, Wy, by);

    const size_t ysmem = (size_t)NV * HB * sizeof(float);   // 16 KB worst case
    attn_kernel<<<dim3(NV / RPB, G, H / HB), 256, ysmem>>>(mask, out);
}

// round 16
// speedup vs baseline: 1.1937x; 1.1937x over previous
#include <cuda_runtime.h>
#include <cuda_bf16.h>
#include <cstdint>

#define G  32
#define NV 64
#define H  256
#define M_ROWS (G * NV)

// Scratch (allocation-free rule: __device__ globals)
__device__ float g_C[M_ROWS * H];
__device__ float g_Y[M_ROWS * H];

// ---------------------------------------------------------------------------
// Stage A: TF32 tensor-core GEMM, no explicit CVT (HMMA.tf32 reads top 19 bits).
//   out[m][n] = sum_h z[m][h] * W[n][h] + b[n]
// Block tile 64(M) x 64(N), KC=32 double-buffered cp.async, 8 warps,
// warp tile 16(M) x 32(N). Grid (H/64, M/64, 2) = 256 blocks.
// ---------------------------------------------------------------------------
#define KC   32
#define LDK  36
#define NCH  (H / KC)   // 8 chunks

__device__ __forceinline__ void cpa16(uint32_t dst, const float* src) {
    asm volatile("cp.async.cg.shared.global [%0], [%1], 16;" :: "r"(dst), "l"(src));
}

__device__ __forceinline__ void mma_tf32(float c[4], const uint32_t a[4], const uint32_t b[2]) {
    asm volatile(
        "mma.sync.aligned.m16n8k8.row.col.f32.tf32.tf32.f32 "
        "{%0,%1,%2,%3}, {%4,%5,%6,%7}, {%8,%9}, {%0,%1,%2,%3};"
        : "+f"(c[0]), "+f"(c[1]), "+f"(c[2]), "+f"(c[3])
        : "r"(a[0]), "r"(a[1]), "r"(a[2]), "r"(a[3]), "r"(b[0]), "r"(b[1]));
}

__global__ void __launch_bounds__(256, 2) gemm_tc_kernel(
    const float* __restrict__ z,
    const float* __restrict__ Wc, const float* __restrict__ bc,
    const float* __restrict__ Wy, const float* __restrict__ by)
{
    const float* __restrict__ W    = blockIdx.z ? Wy : Wc;
    const float* __restrict__ bias = blockIdx.z ? by : bc;
    float* __restrict__ outp       = blockIdx.z ? g_Y : g_C;

    __shared__ float As[2][64 * LDK];
    __shared__ float Bs[2][64 * LDK];

    const int t    = threadIdx.x;
    const int warp = t >> 5;
    const int lane = t & 31;
    const int g    = lane >> 2;
    const int tg   = lane & 3;
    const int wm   = warp & 3;
    const int wn   = warp >> 2;
    const int m0   = blockIdx.y * 64;
    const int n0   = blockIdx.x * 64;

    const int r0s = t >> 3,         kg0 = t & 7;
    const int r1s = (t + 256) >> 3, kg1 = (t + 256) & 7;

    float acc[4][4];
#pragma unroll
    for (int nt = 0; nt < 4; nt++)
#pragma unroll
        for (int i = 0; i < 4; i++) acc[nt][i] = 0.0f;

    auto issue = [&](int c) {
        const int buf = c & 1;
        const int kc0 = c * KC;
        uint32_t asb = (uint32_t)__cvta_generic_to_shared(&As[buf][0]);
        uint32_t bsb = (uint32_t)__cvta_generic_to_shared(&Bs[buf][0]);
        cpa16(asb + (uint32_t)(r0s * LDK + kg0 * 4) * 4, z + (size_t)(m0 + r0s) * H + kc0 + kg0 * 4);
        cpa16(asb + (uint32_t)(r1s * LDK + kg1 * 4) * 4, z + (size_t)(m0 + r1s) * H + kc0 + kg1 * 4);
        cpa16(bsb + (uint32_t)(r0s * LDK + kg0 * 4) * 4, W + (size_t)(n0 + r0s) * H + kc0 + kg0 * 4);
        cpa16(bsb + (uint32_t)(r1s * LDK + kg1 * 4) * 4, W + (size_t)(n0 + r1s) * H + kc0 + kg1 * 4);
        asm volatile("cp.async.commit_group;");
    };

    issue(0);

    for (int c = 0; c < NCH; c++) {
        if (c + 1 < NCH) {
            issue(c + 1);
            asm volatile("cp.async.wait_group 1;");
        } else {
            asm volatile("cp.async.wait_group 0;");
        }
        __syncthreads();

        const uint32_t* as = reinterpret_cast<const uint32_t*>(&As[c & 1][0]);
        const uint32_t* bs = reinterpret_cast<const uint32_t*>(&Bs[c & 1][0]);

#pragma unroll
        for (int ks = 0; ks < KC / 8; ks++) {
            const int kk = ks * 8;
            uint32_t afr[4];
            {
                const uint32_t* ap = as + (wm * 16 + g) * LDK + kk + tg;
                afr[0] = ap[0];
                afr[1] = ap[8 * LDK];
                afr[2] = ap[4];
                afr[3] = ap[8 * LDK + 4];
            }
            uint32_t bfr[4][2];
#pragma unroll
            for (int nt = 0; nt < 4; nt++) {
                const uint32_t* bp = bs + (wn * 32 + nt * 8 + g) * LDK + kk + tg;
                bfr[nt][0] = bp[0];
                bfr[nt][1] = bp[4];
            }
#pragma unroll
            for (int nt = 0; nt < 4; nt++)
                mma_tf32(acc[nt], afr, bfr[nt]);
        }
        __syncthreads();
    }

#pragma unroll
    for (int nt = 0; nt < 4; nt++) {
        const int col = n0 + wn * 32 + nt * 8 + 2 * tg;
        const float b0 = __ldg(&bias[col]);
        const float b1 = __ldg(&bias[col + 1]);
        const int row = m0 + wm * 16 + g;
        float2 o0 = {acc[nt][0] + b0, acc[nt][1] + b1};
        float2 o1 = {acc[nt][2] + b0, acc[nt][3] + b1};
        *reinterpret_cast<float2*>(&outp[(size_t)row * H + col])       = o0;
        *reinterpret_cast<float2*>(&outp[(size_t)(row + 8) * H + col]) = o1;
    }
}

// ---------------------------------------------------------------------------
// Stage B: pairwise sigmoid sum (R12 structure, tanh path — empirically the
// 3-instr/element floor; EX2+RCP at 4 instr was 1.3x slower).
// sigmoid(x) = 0.5*tanh(0.5*x)+0.5 folded into FFMA(imm)/epilogue.
// Block = 256 threads = 32 float2-cols x 8 rows, quarter of H per block,
// 16 KB smem, grid (8,32,4)=1024. PDL: compaction overlaps the GEMM tail;
// cudaGridDependencySynchronize() gates the g_C/g_Y reads.
// ---------------------------------------------------------------------------
#define RPB  8
#define HB   64          // h floats per block
#define HB2  (HB / 2)    // float2 cols per block = 32

__device__ __forceinline__ float tanhx(float x) {
    float th;
    asm("tanh.approx.f32 %0, %1;" : "=f"(th) : "f"(x));
    return th;
}

__global__ void __launch_bounds__(256) attn_kernel(
    const float* __restrict__ mask, float* __restrict__ out)
{
    extern __shared__ float ysh[];       // [NV rows][64 floats] compacted
    __shared__ int acts[NV];
    __shared__ int s_cnt[2];
    __shared__ int s_nact;

    const int gg  = blockIdx.y;
    const int r0  = blockIdx.x * RPB;
    const int hb  = blockIdx.z;          // h quarter
    const int t   = threadIdx.x;
    const int col = t & 31;              // float2 col within quarter
    const int r   = t >> 5;              // 0..7 row slot (== warp id)

    // ---- in-block compaction (independent of GEMM; overlaps it via PDL) ----
    bool act = false;
    unsigned bal = 0;
    if (t < NV) {
        act = (mask[gg * NV + t] > 0.5f);
        bal = __ballot_sync(0xffffffffu, act);
        if ((t & 31) == 0) s_cnt[t >> 5] = __popc(bal);
    }
    __syncthreads();
    if (t < NV) {
        const int warp = t >> 5, lane = t & 31;
        const int a0 = s_cnt[0], a1 = s_cnt[1];
        const int nact = a0 + a1;
        const int pre  = __popc(bal & ((1u << lane) - 1u));
        const int preI = lane - pre;
        const int pos = act ? ((warp ? a0 : 0) + pre)
                            : (nact + (warp ? (32 - a0) : 0) + preI);
        acts[pos] = t;
        if (t == 0) s_nact = nact;
    }
    __syncthreads();

    // ---- wait for the GEMM grid's writes to become visible ----
    cudaGridDependencySynchronize();

    const int nact  = s_nact;
    const int rr    = r0 + r;
    const int row_i = acts[rr];          // rr <= 63 always

    float2* __restrict__ outp = reinterpret_cast<float2*>(
        out + (size_t)gg * NV * H + (size_t)row_i * H + hb * HB) + col;

    if (r0 >= nact) {                    // fully inactive block
        outp[0] = make_float2(0.0f, 0.0f);
        return;
    }

    // ---- compacted fill (issue), then C-row load (overlaps), then wait ----
    {
        const float* __restrict__ ygb = g_Y + (size_t)gg * NV * H + hb * HB;
        const uint32_t sb = (uint32_t)__cvta_generic_to_shared(&ysh[0]);
        const int nch = nact * (HB / 4);          // 16B chunks (16 per row)
        for (int s = t; s < nch; s += 256) {
            const int rw = s >> 4;
            const int q  = s & 15;
            cpa16(sb + (uint32_t)(rw * HB + q * 4) * 4,
                  ygb + (size_t)acts[rw] * H + q * 4);
        }
        asm volatile("cp.async.commit_group;");
    }

    float2 a2, acc;
    {
        const float2 c = __ldg(reinterpret_cast<const float2*>(
            g_C + (size_t)gg * NV * H + (size_t)row_i * H + hb * HB) + col);
        a2.x = 0.5f * c.x;
        a2.y = 0.5f * c.y;
        acc.x = 0.0f;
        acc.y = 0.0f;
    }

    asm volatile("cp.async.wait_group 0;");
    __syncthreads();

    const float2* __restrict__ ys2 = reinterpret_cast<const float2*>(ysh);

    int jj = 0;
    for (; jj + 8 <= nact; jj += 8) {
        float2 yv[8];
#pragma unroll
        for (int u = 0; u < 8; u++) yv[u] = ys2[(jj + u) * HB2 + col];
#pragma unroll
        for (int u = 0; u < 8; u++) {
            acc.x += tanhx(fmaf(0.5f, yv[u].x, a2.x));
            acc.y += tanhx(fmaf(0.5f, yv[u].y, a2.y));
        }
    }
    for (; jj < nact; jj++) {
        const float2 y = ys2[jj * HB2 + col];
        acc.x += tanhx(fmaf(0.5f, y.x, a2.x));
        acc.y += tanhx(fmaf(0.5f, y.y, a2.y));
    }

    const float inv    = 1.0f / (float)nact;
    const float half_n = 0.5f * (float)nact;
    float2 v;
    if (rr < nact) {                     // straddling block's tail rows -> 0
        v.x = (0.5f * acc.x + half_n) * inv;
        v.y = (0.5f * acc.y + half_n) * inv;
    } else {
        v.x = 0.0f;
        v.y = 0.0f;
    }
    outp[0] = v;
}

// ---------------------------------------------------------------------------
// kernel_launch: gemm, then attn with PDL (programmatic stream serialization)
// so attn's prologue overlaps the gemm tail. Falls back to a plain launch if
// the PDL launch fails.
// ---------------------------------------------------------------------------
extern "C" void kernel_launch(void* const* d_in, const int* in_sizes, int n_in,
                              void* d_out, int out_size)
{
    const float *z = nullptr, *mask = nullptr;
    const float *Wc = nullptr, *bc = nullptr, *Wy = nullptr, *by = nullptr;

    for (int i = 0; i < n_in; i++) {
        int s = in_sizes[i];
        const float* p = (const float*)d_in[i];
        if (s == M_ROWS * H)       z = p;
        else if (s == M_ROWS)      mask = p;
        else if (s == H * H)       { if (!Wc) Wc = p; else Wy = p; }
        else if (s == H)           { if (!bc) bc = p; else by = p; }
    }

    float* out = (float*)d_out;

    gemm_tc_kernel<<<dim3(H / 64, M_ROWS / 64, 2), 256>>>(z, Wc, bc, Wy, by);

    const size_t ysmem = (size_t)NV * HB * sizeof(float);   // 16 KB worst case

    cudaLaunchConfig_t cfg = {};
    cfg.gridDim  = dim3(NV / RPB, G, H / HB);
    cfg.blockDim = dim3(256, 1, 1);
    cfg.dynamicSmemBytes = ysmem;
    cfg.stream = 0;
    cudaLaunchAttribute at[1];
    at[0].id = cudaLaunchAttributeProgrammaticStreamSerialization;
    at[0].val.programmaticStreamSerializationAllowed = 1;
    cfg.attrs = at;
    cfg.numAttrs = 1;

    cudaError_t e = cudaLaunchKernelEx(&cfg, attn_kernel, mask, out);
    if (e != cudaSuccess) {
        // fallback: plain launch (cudaGridDependencySynchronize is a no-op
        // without PDL edges)
        attn_kernel<<<dim3(NV / RPB, G, H / HB), 256, ysmem>>>(mask, out);
    }
}